// round 9
// baseline (speedup 1.0000x reference)
#include <cuda_runtime.h>

#define BATCH     65536
#define TM        64
#define NTH       256
#define RES_SCALE 0.70710678118654752440f
#define GAMMA_C   1.5f

// folded BN affine tables: y = acc*A + C
#define OFF_IN    0
#define OFF_SH0   320
#define OFF_SH1   576
#define OFF_INIT  832
#define OFF_STEP  1344
#define OFF_ATT   3904
#define AC_TOTAL  4304

__device__ float g_A[AC_TOTAL];
__device__ float g_C[AC_TOTAL];

// activation layout: element (col, r) -> col*64 + (r ^ (col & 0x1C))
#define SWZ(col, r) ((col) * 64 + ((r) ^ ((col) & 0x1C)))

#define FMA2(acc, a, b) \
    asm("fma.rn.f32x2 %0, %1, %2, %0;" : "+l"(acc) : "l"(a), "l"(b))
#define PACKDUP(dst, v) \
    asm("mov.b64 %0, {%1, %1};" : "=l"(dst) : "r"(__float_as_uint(v)))
#define UNPACK2(lo, hi, v) \
    asm("mov.b64 {%0, %1}, %2;" : "=f"(lo), "=f"(hi) : "l"(v))

__device__ __forceinline__ void cp16(unsigned dst, const float* src) {
    asm volatile("cp.async.ca.shared.global [%0], [%1], 16;\n"
                 :: "r"(dst), "l"(src));
}
#define CP_COMMIT() asm volatile("cp.async.commit_group;\n" ::: "memory")
#define CP_WAIT0()  asm volatile("cp.async.wait_group 0;\n" ::: "memory")
#define CP_WAIT1()  asm volatile("cp.async.wait_group 1;\n" ::: "memory")

__global__ void prep_kernel(
    const float* __restrict__ in_bn,
    const float* __restrict__ sh_b0, const float* __restrict__ sh_bn0,
    const float* __restrict__ sh_b1, const float* __restrict__ sh_bn1,
    const float* __restrict__ init_b, const float* __restrict__ init_bn,
    const float* __restrict__ step_b, const float* __restrict__ step_bn,
    const float* __restrict__ att_b,  const float* __restrict__ att_bn)
{
    int idx = blockIdx.x * blockDim.x + threadIdx.x;
    if (idx >= AC_TOTAL) return;
    float s, bb, m, v, bias;
    if (idx < OFF_SH0) {
        int c = idx;
        s = in_bn[c]; bb = in_bn[320 + c]; m = in_bn[640 + c]; v = in_bn[960 + c];
        bias = 0.f;
    } else if (idx < OFF_SH1) {
        int c = idx - OFF_SH0;
        s = sh_bn0[c]; bb = sh_bn0[256 + c]; m = sh_bn0[512 + c]; v = sh_bn0[768 + c];
        bias = sh_b0[c];
    } else if (idx < OFF_INIT) {
        int c = idx - OFF_SH1;
        s = sh_bn1[c]; bb = sh_bn1[256 + c]; m = sh_bn1[512 + c]; v = sh_bn1[768 + c];
        bias = sh_b1[c];
    } else if (idx < OFF_STEP) {
        int q = (idx - OFF_INIT) >> 8;
        int c = (idx - OFF_INIT) & 255;
        const float* p = init_bn + q * 1024;
        s = p[c]; bb = p[256 + c]; m = p[512 + c]; v = p[768 + c];
        bias = init_b[q * 256 + c];
    } else if (idx < OFF_ATT) {
        int q = (idx - OFF_STEP) >> 8;
        int c = (idx - OFF_STEP) & 255;
        const float* p = step_bn + q * 1024;
        s = p[c]; bb = p[256 + c]; m = p[512 + c]; v = p[768 + c];
        bias = step_b[q * 256 + c];
    } else {
        int q = (idx - OFF_ATT) / 80;
        int c = (idx - OFF_ATT) % 80;
        const float* p = att_bn + q * 320;
        s = p[c]; bb = p[80 + c]; m = p[160 + c]; v = p[240 + c];
        bias = att_b[q * 80 + c];
    }
    float A = s * rsqrtf(v + 1e-5f);
    g_A[idx] = A;
    g_C[idx] = (bias - m) * A + bb;
}

// One fused GLU layer: dst[:,j] = GLU(BN(src @ W + b)) [+ residual]
// src/dst are smem, column-major [col][64] with XOR swizzle SWZ.
// Thread t: rows r0..r0+3, o-cols {c4..c4+3, 64+c4..} + g-cols (+128).
// Warp layout: 4 row-groups x 8 col-groups -> every W address shared by 4
// lanes (1 wavefront per W load), x broadcast 8-way (1 wavefront).
// Weights pipelined via cp.async in 16-k chunks through a 3-buffer ring.
template<bool USE_MASK, bool RESID>
__device__ __forceinline__ void glu_layer(
    int K, const float* __restrict__ Wg, int acoff,
    const float* src, float* dst, float* ws, unsigned ws_s, const float* mg,
    int t, int r0, int c4)
{
    unsigned long long acc[4][8];
#pragma unroll
    for (int i = 0; i < 4; i++)
#pragma unroll
        for (int j = 0; j < 8; j++) acc[i][j] = 0ull;

    const int nch = K >> 4;     // 16-k chunks, 4096 floats each

    // prologue: stage chunks 0 and 1
    {
        const float* s0 = Wg + t * 4;
#pragma unroll
        for (int i = 0; i < 4; i++)
            cp16(ws_s + (t + i * 256) * 16, s0 + i * 1024);
        CP_COMMIT();
        if (nch > 1) {
            const float* s1 = Wg + 4096 + t * 4;
#pragma unroll
            for (int i = 0; i < 4; i++)
                cp16(ws_s + 16384 + (t + i * 256) * 16, s1 + i * 1024);
            CP_COMMIT();
        }
    }

    for (int c = 0; c < nch; c++) {
        if (c + 1 < nch) CP_WAIT1(); else CP_WAIT0();
        __syncthreads();
        if (c + 2 < nch) {
            int b = (c + 2) % 3;
            const float* sp = Wg + (c + 2) * 4096 + t * 4;
#pragma unroll
            for (int i = 0; i < 4; i++)
                cp16(ws_s + b * 16384 + (t + i * 256) * 16, sp + i * 1024);
            CP_COMMIT();
        }
        const float* buf = ws + (c % 3) * 4096;

        float4 mvec;
        if (USE_MASK && c >= 4) {   // k >= 64: group constant within 16-k chunk
            int g = 60 + c;
            mvec = *(const float4*)(mg + g * 64 + (r0 ^ (g & 0x1C)));
        }
#pragma unroll 8
        for (int ki = 0; ki < 16; ki++) {
            int k = c * 16 + ki;
            float4 xv = *(const float4*)(src + k * 64 + (r0 ^ (k & 0x1C)));
            if (USE_MASK) {
                if (c >= 4) {
                    xv.x *= mvec.x; xv.y *= mvec.y; xv.z *= mvec.z; xv.w *= mvec.w;
                } else {
                    float4 mv = *(const float4*)(mg + k * 64 + (r0 ^ (k & 0x1C)));
                    xv.x *= mv.x; xv.y *= mv.y; xv.z *= mv.z; xv.w *= mv.w;
                }
            }
            unsigned long long xd[4];
            PACKDUP(xd[0], xv.x);
            PACKDUP(xd[1], xv.y);
            PACKDUP(xd[2], xv.z);
            PACKDUP(xd[3], xv.w);

            const float* wr = buf + ki * 256 + c4;
            ulonglong2 w0 = *(const ulonglong2*)(wr);
            ulonglong2 w1 = *(const ulonglong2*)(wr + 64);
            ulonglong2 w2 = *(const ulonglong2*)(wr + 128);
            ulonglong2 w3 = *(const ulonglong2*)(wr + 192);
            unsigned long long wp[8] = {w0.x, w0.y, w1.x, w1.y,
                                        w2.x, w2.y, w3.x, w3.y};
#pragma unroll
            for (int rr = 0; rr < 4; rr++)
#pragma unroll
                for (int j = 0; j < 8; j++)
                    FMA2(acc[rr][j], xd[rr], wp[j]);
        }
    }
    __syncthreads();

    // epilogue: BN fold + GLU + optional residual
    float ov[4][8], gv[4][8];
#pragma unroll
    for (int rr = 0; rr < 4; rr++)
#pragma unroll
        for (int j = 0; j < 4; j++) {
            UNPACK2(ov[rr][j * 2], ov[rr][j * 2 + 1], acc[rr][j]);
            UNPACK2(gv[rr][j * 2], gv[rr][j * 2 + 1], acc[rr][4 + j]);
        }

#pragma unroll
    for (int h = 0; h < 2; h++) {
#pragma unroll
        for (int i = 0; i < 4; i++) {
            int lc  = h * 4 + i;
            int col = h * 64 + c4 + i;
            float Ao = g_A[acoff + col],       Co = g_C[acoff + col];
            float Ag = g_A[acoff + 128 + col], Cg = g_C[acoff + 128 + col];
            float y[4];
#pragma unroll
            for (int rr = 0; rr < 4; rr++) {
                float oo = fmaf(ov[rr][lc], Ao, Co);
                float gg = fmaf(gv[rr][lc], Ag, Cg);
                float sg = 1.f / (1.f + __expf(-gg));
                y[rr] = oo * sg;
            }
            float* dp = dst + col * 64 + (r0 ^ (col & 0x1C));
            if (RESID) {
                float4 old = *(float4*)dp;
                y[0] = (old.x + y[0]) * RES_SCALE;
                y[1] = (old.y + y[1]) * RES_SCALE;
                y[2] = (old.z + y[2]) * RES_SCALE;
                y[3] = (old.w + y[3]) * RES_SCALE;
            }
            *(float4*)dp = make_float4(y[0], y[1], y[2], y[3]);
        }
    }
    __syncthreads();
}

__global__ void __launch_bounds__(NTH, 1) tabnet_kernel(
    const float* __restrict__ x_num, const int* __restrict__ x_cat,
    const float* __restrict__ emb_W,
    const float* __restrict__ sh_W0, const float* __restrict__ sh_W1,
    const float* __restrict__ init_W, const float* __restrict__ step_W,
    const float* __restrict__ att_W, const float* __restrict__ out_W,
    const float* __restrict__ out_b, float* __restrict__ out)
{
    extern __shared__ float sm[];
    float* xs = sm;                 // [320][64] swizzled
    float* hs = xs + 320 * 64;      // [128][64] swizzled
    float* ws = hs + 128 * 64;      // 12288 floats: 3 cp.async bufs / att stage / logits
    float* mg = ws + 12288;         // [80][64]  mask per group, swizzled
    float* pr = mg + 80 * 64;       // [64][80]  prior, row-major
    float* ds = pr + 64 * 80;       // [64][64]  decision sum (phys copy of hs layout)

    const int t    = threadIdx.x;
    const int w    = t >> 5;
    const int lane = t & 31;
    // warp = 4 row-groups x 8 col-groups: 4-way W sharing, 8-way x broadcast
    const int r0 = ((w & 3) << 4) + ((lane >> 3) << 2);   // 0..60 step 4
    const int c4 = ((w >> 2) << 5) + ((lane & 7) << 2);   // 0..60 step 4
    const int rowb = blockIdx.x * TM;
    const unsigned ws_s = (unsigned)__cvta_generic_to_shared(ws);

    // ---- load x_num with folded input BN ----
#pragma unroll
    for (int i = 0; i < 16; i++) {
        int idx = t + i * 256;          // 4096 elems
        int r = idx & 63, f = idx >> 6;
        xs[SWZ(f, r)] = x_num[(rowb + r) * 64 + f] * g_A[f] + g_C[f];
    }
    // ---- embeddings (16 cats x 16 dims) with folded input BN ----
#pragma unroll
    for (int i = 0; i < 4; i++) {
        int p = t + i * 256;            // 1024 (row,cat) pairs
        int r = p & 63, c = p >> 6;
        int id = x_cat[(rowb + r) * 16 + c];
        const float* e = emb_W + (c * 1000 + id) * 16;
#pragma unroll
        for (int j = 0; j < 16; j++) {
            int f = 64 + c * 16 + j;
            xs[SWZ(f, r)] = e[j] * g_A[f] + g_C[f];
        }
    }
    for (int i = t; i < 80 * 64; i += NTH) mg[i] = 1.f;
    for (int i = t; i < 64 * 80; i += NTH) pr[i] = 1.f;
    for (int i = t; i < 64 * 64; i += NTH) ds[i] = 0.f;
    __syncthreads();

    // ---- init pass: ft_shared + ft_indep(init) ----
    glu_layer<true,  false>(320, sh_W0, OFF_SH0, xs, hs, ws, ws_s, mg, t, r0, c4);
    glu_layer<false, true >(128, sh_W1, OFF_SH1, hs, hs, ws, ws_s, mg, t, r0, c4);
    glu_layer<false, true >(128, init_W,             OFF_INIT,       hs, hs, ws, ws_s, mg, t, r0, c4);
    glu_layer<false, true >(128, init_W + 128 * 256, OFF_INIT + 256, hs, hs, ws, ws_s, mg, t, r0, c4);

    for (int s = 0; s < 5; s++) {
        // ---- attention GEMM: logits = BN(a @ att_W[s] + b) * prior ----
        const float* aw = att_W + s * 64 * 80;
        for (int i = t; i < 5120; i += NTH) ws[i] = aw[i];
        __syncthreads();

        float acc[4][5];
#pragma unroll
        for (int rr = 0; rr < 4; rr++)
#pragma unroll
            for (int j = 0; j < 5; j++) acc[rr][j] = 0.f;
        const int ra = (t >> 4) << 2;       // rows 0..60 step 4
        const int c5 = (t & 15) * 5;
#pragma unroll 4
        for (int kk = 0; kk < 64; kk++) {
            int col = 64 + kk;
            float4 av = *(const float4*)(hs + col * 64 + (ra ^ (col & 0x1C)));
            float arr[4] = {av.x, av.y, av.z, av.w};
#pragma unroll
            for (int j = 0; j < 5; j++) {
                float wv = ws[kk * 80 + c5 + j];
#pragma unroll
                for (int rr = 0; rr < 4; rr++)
                    acc[rr][j] = fmaf(arr[rr], wv, acc[rr][j]);
            }
        }
        __syncthreads();

        // write logits (BN-folded * prior) into ws as [row][80]
#pragma unroll
        for (int j = 0; j < 5; j++) {
            int g = c5 + j;
            float A = g_A[OFF_ATT + s * 80 + g], C = g_C[OFF_ATT + s * 80 + g];
#pragma unroll
            for (int rr = 0; rr < 4; rr++) {
                int r = ra + rr;
                ws[r * 80 + g] = fmaf(acc[rr][j], A, C) * pr[r * 80 + g];
            }
        }
        __syncthreads();

        // ---- sparsemax via Michelot's exact simplex projection ----
        if (t < 64) {
            const float* z = ws + t * 80;
            float S = 0.f;
            for (int i = 0; i < 80; i++) S += z[i];
            int k = 80;
            float tau = (S - 1.f) / 80.f;
            for (int it = 0; it < 80; it++) {
                float S2 = 0.f; int k2 = 0;
                for (int i = 0; i < 80; i++) {
                    float zi = z[i];
                    if (zi > tau) { S2 += zi; k2++; }
                }
                if (k2 == k) break;
                k = k2;
                tau = (S2 - 1.f) / (float)k2;
            }
            for (int g = 0; g < 80; g++) {
                float m_ = z[g] - tau;
                m_ = m_ > 0.f ? m_ : 0.f;
                mg[SWZ(g, t)] = m_;
                pr[t * 80 + g] *= (GAMMA_C - m_);
            }
        }
        __syncthreads();

        // ---- masked ft pass: ft_shared(mask*x) -> ft_indep(step s) ----
        const float* sw = step_W + s * 2 * 128 * 256;
        glu_layer<true,  false>(320, sh_W0, OFF_SH0, xs, hs, ws, ws_s, mg, t, r0, c4);
        glu_layer<false, true >(128, sh_W1, OFF_SH1, hs, hs, ws, ws_s, mg, t, r0, c4);
        glu_layer<false, true >(128, sw,             OFF_STEP + (s * 2) * 256,     hs, hs, ws, ws_s, mg, t, r0, c4);
        glu_layer<false, true >(128, sw + 128 * 256, OFF_STEP + (s * 2 + 1) * 256, hs, hs, ws, ws_s, mg, t, r0, c4);

        // ---- decision_sum += relu(d) (d = hs cols 0..63; same phys layout) ----
#pragma unroll
        for (int i = 0; i < 16; i++) {
            int idx = t + i * 256;      // 4096 elems
            float v = hs[idx];
            ds[idx] += v > 0.f ? v : 0.f;
        }
        __syncthreads();
    }

    // ---- final: out = decision_sum @ out_W + out_b ----
    if (t < 64) {
        float sacc = 0.f;
#pragma unroll
        for (int j = 0; j < 64; j++)
            sacc = fmaf(ds[SWZ(j, t)], out_W[j], sacc);
        out[rowb + t] = sacc + out_b[0];
    }
}

#define SMEM_FLOATS (320*64 + 128*64 + 12288 + 80*64 + 64*80 + 64*64)
#define SMEM_BYTES  (SMEM_FLOATS * 4)

extern "C" void kernel_launch(void* const* d_in, const int* in_sizes, int n_in,
                              void* d_out, int out_size)
{
    const float* x_num   = (const float*)d_in[0];
    const int*   x_cat   = (const int*)  d_in[1];
    const float* emb_W   = (const float*)d_in[2];
    const float* in_bn   = (const float*)d_in[3];
    const float* sh_W0   = (const float*)d_in[4];
    const float* sh_b0   = (const float*)d_in[5];
    const float* sh_bn0  = (const float*)d_in[6];
    const float* sh_W1   = (const float*)d_in[7];
    const float* sh_b1   = (const float*)d_in[8];
    const float* sh_bn1  = (const float*)d_in[9];
    const float* init_W  = (const float*)d_in[10];
    const float* init_b  = (const float*)d_in[11];
    const float* init_bn = (const float*)d_in[12];
    const float* step_W  = (const float*)d_in[13];
    const float* step_b  = (const float*)d_in[14];
    const float* step_bn = (const float*)d_in[15];
    const float* att_W   = (const float*)d_in[16];
    const float* att_b   = (const float*)d_in[17];
    const float* att_bn  = (const float*)d_in[18];
    const float* out_W   = (const float*)d_in[19];
    const float* out_b   = (const float*)d_in[20];
    float* out = (float*)d_out;

    cudaFuncSetAttribute(tabnet_kernel,
                         cudaFuncAttributeMaxDynamicSharedMemorySize, SMEM_BYTES);

    prep_kernel<<<(AC_TOTAL + 255) / 256, 256>>>(
        in_bn, sh_b0, sh_bn0, sh_b1, sh_bn1,
        init_b, init_bn, step_b, step_bn, att_b, att_bn);

    tabnet_kernel<<<BATCH / TM, NTH, SMEM_BYTES>>>(
        x_num, x_cat, emb_W, sh_W0, sh_W1, init_W, step_W,
        att_W, out_W, out_b, out);
}

// round 10
// speedup vs baseline: 1.0015x; 1.0015x over previous
#include <cuda_runtime.h>

#define BATCH     65536
#define TM        64
#define NTH       256
#define RES_SCALE 0.70710678118654752440f
#define GAMMA_C   1.5f

// folded BN affine tables: y = acc*A + C
#define OFF_IN    0
#define OFF_SH0   320
#define OFF_SH1   576
#define OFF_INIT  832
#define OFF_STEP  1344
#define OFF_ATT   3904
#define AC_TOTAL  4304

__device__ float g_A[AC_TOTAL];
__device__ float g_C[AC_TOTAL];

// activation layout: element (col, r) -> col*64 + (r ^ (col & 0x1C))
#define SWZ(col, r) ((col) * 64 + ((r) ^ ((col) & 0x1C)))

#define FMA2(acc, a, b) \
    asm("fma.rn.f32x2 %0, %1, %2, %0;" : "+l"(acc) : "l"(a), "l"(b))
#define PACKDUP(dst, v) \
    asm("mov.b64 %0, {%1, %1};" : "=l"(dst) : "r"(__float_as_uint(v)))
#define UNPACK2(lo, hi, v) \
    asm("mov.b64 {%0, %1}, %2;" : "=f"(lo), "=f"(hi) : "l"(v))

__device__ __forceinline__ void cp16(unsigned dst, const float* src) {
    asm volatile("cp.async.ca.shared.global [%0], [%1], 16;\n"
                 :: "r"(dst), "l"(src));
}
#define CP_COMMIT() asm volatile("cp.async.commit_group;\n" ::: "memory")
#define CP_WAIT0()  asm volatile("cp.async.wait_group 0;\n" ::: "memory")
#define CP_WAIT1()  asm volatile("cp.async.wait_group 1;\n" ::: "memory")

__global__ void prep_kernel(
    const float* __restrict__ in_bn,
    const float* __restrict__ sh_b0, const float* __restrict__ sh_bn0,
    const float* __restrict__ sh_b1, const float* __restrict__ sh_bn1,
    const float* __restrict__ init_b, const float* __restrict__ init_bn,
    const float* __restrict__ step_b, const float* __restrict__ step_bn,
    const float* __restrict__ att_b,  const float* __restrict__ att_bn)
{
    int idx = blockIdx.x * blockDim.x + threadIdx.x;
    if (idx >= AC_TOTAL) return;
    float s, bb, m, v, bias;
    if (idx < OFF_SH0) {
        int c = idx;
        s = in_bn[c]; bb = in_bn[320 + c]; m = in_bn[640 + c]; v = in_bn[960 + c];
        bias = 0.f;
    } else if (idx < OFF_SH1) {
        int c = idx - OFF_SH0;
        s = sh_bn0[c]; bb = sh_bn0[256 + c]; m = sh_bn0[512 + c]; v = sh_bn0[768 + c];
        bias = sh_b0[c];
    } else if (idx < OFF_INIT) {
        int c = idx - OFF_SH1;
        s = sh_bn1[c]; bb = sh_bn1[256 + c]; m = sh_bn1[512 + c]; v = sh_bn1[768 + c];
        bias = sh_b1[c];
    } else if (idx < OFF_STEP) {
        int q = (idx - OFF_INIT) >> 8;
        int c = (idx - OFF_INIT) & 255;
        const float* p = init_bn + q * 1024;
        s = p[c]; bb = p[256 + c]; m = p[512 + c]; v = p[768 + c];
        bias = init_b[q * 256 + c];
    } else if (idx < OFF_ATT) {
        int q = (idx - OFF_STEP) >> 8;
        int c = (idx - OFF_STEP) & 255;
        const float* p = step_bn + q * 1024;
        s = p[c]; bb = p[256 + c]; m = p[512 + c]; v = p[768 + c];
        bias = step_b[q * 256 + c];
    } else {
        int q = (idx - OFF_ATT) / 80;
        int c = (idx - OFF_ATT) % 80;
        const float* p = att_bn + q * 320;
        s = p[c]; bb = p[80 + c]; m = p[160 + c]; v = p[240 + c];
        bias = att_b[q * 80 + c];
    }
    float A = s * rsqrtf(v + 1e-5f);
    g_A[idx] = A;
    g_C[idx] = (bias - m) * A + bb;
}

// One fused GLU layer: dst[:,j] = GLU(BN(src @ W + b)) [+ residual]
// src/dst are smem, column-major [col][64] with XOR swizzle SWZ.
// Thread t: rows r0..r0+3, o-cols {c4..c4+3, 64+c4..} + g-cols (+128).
// Warp layout: 4 row-groups x 8 col-groups -> every W address shared by 4
// lanes (1 wavefront per W load), x broadcast 8-way (1 wavefront).
// Weights pipelined via cp.async in 16-k chunks through a 3-buffer ring.
template<bool USE_MASK, bool RESID>
__device__ __forceinline__ void glu_layer(
    int K, const float* __restrict__ Wg, int acoff,
    const float* src, float* dst, float* ws, unsigned ws_s, const float* mg,
    int t, int r0, int c4)
{
    unsigned long long acc[4][8];
#pragma unroll
    for (int i = 0; i < 4; i++)
#pragma unroll
        for (int j = 0; j < 8; j++) acc[i][j] = 0ull;

    const int nch = K >> 4;     // 16-k chunks, 4096 floats each

    // prologue: stage chunks 0 and 1
    {
        const float* s0 = Wg + t * 4;
#pragma unroll
        for (int i = 0; i < 4; i++)
            cp16(ws_s + (t + i * 256) * 16, s0 + i * 1024);
        CP_COMMIT();
        if (nch > 1) {
            const float* s1 = Wg + 4096 + t * 4;
#pragma unroll
            for (int i = 0; i < 4; i++)
                cp16(ws_s + 16384 + (t + i * 256) * 16, s1 + i * 1024);
            CP_COMMIT();
        }
    }

    for (int c = 0; c < nch; c++) {
        if (c + 1 < nch) CP_WAIT1(); else CP_WAIT0();
        __syncthreads();
        if (c + 2 < nch) {
            int b = (c + 2) % 3;
            const float* sp = Wg + (c + 2) * 4096 + t * 4;
#pragma unroll
            for (int i = 0; i < 4; i++)
                cp16(ws_s + b * 16384 + (t + i * 256) * 16, sp + i * 1024);
            CP_COMMIT();
        }
        const float* buf = ws + (c % 3) * 4096;

        float4 mvec;
        if (USE_MASK && c >= 4) {   // k >= 64: group constant within 16-k chunk
            int g = 60 + c;
            mvec = *(const float4*)(mg + g * 64 + (r0 ^ (g & 0x1C)));
        }
#pragma unroll 8
        for (int ki = 0; ki < 16; ki++) {
            int k = c * 16 + ki;
            float4 xv = *(const float4*)(src + k * 64 + (r0 ^ (k & 0x1C)));
            if (USE_MASK) {
                if (c >= 4) {
                    xv.x *= mvec.x; xv.y *= mvec.y; xv.z *= mvec.z; xv.w *= mvec.w;
                } else {
                    float4 mv = *(const float4*)(mg + k * 64 + (r0 ^ (k & 0x1C)));
                    xv.x *= mv.x; xv.y *= mv.y; xv.z *= mv.z; xv.w *= mv.w;
                }
            }
            unsigned long long xd[4];
            PACKDUP(xd[0], xv.x);
            PACKDUP(xd[1], xv.y);
            PACKDUP(xd[2], xv.z);
            PACKDUP(xd[3], xv.w);

            const float* wr = buf + ki * 256 + c4;
            ulonglong2 w0 = *(const ulonglong2*)(wr);
            ulonglong2 w1 = *(const ulonglong2*)(wr + 64);
            ulonglong2 w2 = *(const ulonglong2*)(wr + 128);
            ulonglong2 w3 = *(const ulonglong2*)(wr + 192);
            unsigned long long wp[8] = {w0.x, w0.y, w1.x, w1.y,
                                        w2.x, w2.y, w3.x, w3.y};
#pragma unroll
            for (int rr = 0; rr < 4; rr++)
#pragma unroll
                for (int j = 0; j < 8; j++)
                    FMA2(acc[rr][j], xd[rr], wp[j]);
        }
    }
    __syncthreads();

    // epilogue: BN fold + GLU + optional residual
    float ov[4][8], gv[4][8];
#pragma unroll
    for (int rr = 0; rr < 4; rr++)
#pragma unroll
        for (int j = 0; j < 4; j++) {
            UNPACK2(ov[rr][j * 2], ov[rr][j * 2 + 1], acc[rr][j]);
            UNPACK2(gv[rr][j * 2], gv[rr][j * 2 + 1], acc[rr][4 + j]);
        }

#pragma unroll
    for (int h = 0; h < 2; h++) {
#pragma unroll
        for (int i = 0; i < 4; i++) {
            int lc  = h * 4 + i;
            int col = h * 64 + c4 + i;
            float Ao = g_A[acoff + col],       Co = g_C[acoff + col];
            float Ag = g_A[acoff + 128 + col], Cg = g_C[acoff + 128 + col];
            float y[4];
#pragma unroll
            for (int rr = 0; rr < 4; rr++) {
                float oo = fmaf(ov[rr][lc], Ao, Co);
                float gg = fmaf(gv[rr][lc], Ag, Cg);
                float sg = 1.f / (1.f + __expf(-gg));
                y[rr] = oo * sg;
            }
            float* dp = dst + col * 64 + (r0 ^ (col & 0x1C));
            if (RESID) {
                float4 old = *(float4*)dp;
                y[0] = (old.x + y[0]) * RES_SCALE;
                y[1] = (old.y + y[1]) * RES_SCALE;
                y[2] = (old.z + y[2]) * RES_SCALE;
                y[3] = (old.w + y[3]) * RES_SCALE;
            }
            *(float4*)dp = make_float4(y[0], y[1], y[2], y[3]);
        }
    }
    __syncthreads();
}

__global__ void __launch_bounds__(NTH, 1) tabnet_kernel(
    const float* __restrict__ x_num, const int* __restrict__ x_cat,
    const float* __restrict__ emb_W,
    const float* __restrict__ sh_W0, const float* __restrict__ sh_W1,
    const float* __restrict__ init_W, const float* __restrict__ step_W,
    const float* __restrict__ att_W, const float* __restrict__ out_W,
    const float* __restrict__ out_b, float* __restrict__ out)
{
    extern __shared__ float sm[];
    float* xs = sm;                 // [320][64] swizzled
    float* hs = xs + 320 * 64;      // [128][64] swizzled
    float* ws = hs + 128 * 64;      // 12288 floats: 3 cp.async bufs / att stage / logits
    float* mg = ws + 12288;         // [80][64]  mask per group, swizzled
    float* pr = mg + 80 * 64;       // [64][80]  prior, row-major
    float* ds = pr + 64 * 80;       // [64][64]  decision sum (phys copy of hs layout)

    const int t    = threadIdx.x;
    const int w    = t >> 5;
    const int lane = t & 31;
    // warp = 4 row-groups x 8 col-groups: 4-way W sharing, 8-way x broadcast
    const int r0 = ((w & 3) << 4) + ((lane >> 3) << 2);   // 0..60 step 4
    const int c4 = ((w >> 2) << 5) + ((lane & 7) << 2);   // 0..60 step 4
    const int rowb = blockIdx.x * TM;
    const unsigned ws_s = (unsigned)__cvta_generic_to_shared(ws);

    // ---- load x_num with folded input BN ----
#pragma unroll
    for (int i = 0; i < 16; i++) {
        int idx = t + i * 256;          // 4096 elems
        int r = idx & 63, f = idx >> 6;
        xs[SWZ(f, r)] = x_num[(rowb + r) * 64 + f] * g_A[f] + g_C[f];
    }
    // ---- embeddings (16 cats x 16 dims) with folded input BN ----
#pragma unroll
    for (int i = 0; i < 4; i++) {
        int p = t + i * 256;            // 1024 (row,cat) pairs
        int r = p & 63, c = p >> 6;
        int id = x_cat[(rowb + r) * 16 + c];
        const float* e = emb_W + (c * 1000 + id) * 16;
#pragma unroll
        for (int j = 0; j < 16; j++) {
            int f = 64 + c * 16 + j;
            xs[SWZ(f, r)] = e[j] * g_A[f] + g_C[f];
        }
    }
    for (int i = t; i < 80 * 64; i += NTH) mg[i] = 1.f;
    for (int i = t; i < 64 * 80; i += NTH) pr[i] = 1.f;
    for (int i = t; i < 64 * 64; i += NTH) ds[i] = 0.f;
    __syncthreads();

    // ---- init pass: ft_shared + ft_indep(init) ----
    glu_layer<true,  false>(320, sh_W0, OFF_SH0, xs, hs, ws, ws_s, mg, t, r0, c4);
    glu_layer<false, true >(128, sh_W1, OFF_SH1, hs, hs, ws, ws_s, mg, t, r0, c4);
    glu_layer<false, true >(128, init_W,             OFF_INIT,       hs, hs, ws, ws_s, mg, t, r0, c4);
    glu_layer<false, true >(128, init_W + 128 * 256, OFF_INIT + 256, hs, hs, ws, ws_s, mg, t, r0, c4);

    for (int s = 0; s < 5; s++) {
        // ---- attention GEMM: logits = BN(a @ att_W[s] + b) * prior ----
        const float* aw = att_W + s * 64 * 80;
        for (int i = t; i < 5120; i += NTH) ws[i] = aw[i];
        __syncthreads();

        float acc[4][5];
#pragma unroll
        for (int rr = 0; rr < 4; rr++)
#pragma unroll
            for (int j = 0; j < 5; j++) acc[rr][j] = 0.f;
        const int ra = (t >> 4) << 2;       // rows 0..60 step 4
        const int c5 = (t & 15) * 5;
#pragma unroll 4
        for (int kk = 0; kk < 64; kk++) {
            int col = 64 + kk;
            float4 av = *(const float4*)(hs + col * 64 + (ra ^ (col & 0x1C)));
            float arr[4] = {av.x, av.y, av.z, av.w};
#pragma unroll
            for (int j = 0; j < 5; j++) {
                float wv = ws[kk * 80 + c5 + j];
#pragma unroll
                for (int rr = 0; rr < 4; rr++)
                    acc[rr][j] = fmaf(arr[rr], wv, acc[rr][j]);
            }
        }
        __syncthreads();

        // write logits (BN-folded * prior) into ws as [row][80]
#pragma unroll
        for (int j = 0; j < 5; j++) {
            int g = c5 + j;
            float A = g_A[OFF_ATT + s * 80 + g], C = g_C[OFF_ATT + s * 80 + g];
#pragma unroll
            for (int rr = 0; rr < 4; rr++) {
                int r = ra + rr;
                ws[r * 80 + g] = fmaf(acc[rr][j], A, C) * pr[r * 80 + g];
            }
        }
        __syncthreads();

        // ---- sparsemax via Michelot's exact simplex projection ----
        if (t < 64) {
            const float* z = ws + t * 80;
            float S = 0.f;
            for (int i = 0; i < 80; i++) S += z[i];
            int k = 80;
            float tau = (S - 1.f) / 80.f;
            for (int it = 0; it < 80; it++) {
                float S2 = 0.f; int k2 = 0;
                for (int i = 0; i < 80; i++) {
                    float zi = z[i];
                    if (zi > tau) { S2 += zi; k2++; }
                }
                if (k2 == k) break;
                k = k2;
                tau = (S2 - 1.f) / (float)k2;
            }
            for (int g = 0; g < 80; g++) {
                float m_ = z[g] - tau;
                m_ = m_ > 0.f ? m_ : 0.f;
                mg[SWZ(g, t)] = m_;
                pr[t * 80 + g] *= (GAMMA_C - m_);
            }
        }
        __syncthreads();

        // ---- masked ft pass: ft_shared(mask*x) -> ft_indep(step s) ----
        const float* sw = step_W + s * 2 * 128 * 256;
        glu_layer<true,  false>(320, sh_W0, OFF_SH0, xs, hs, ws, ws_s, mg, t, r0, c4);
        glu_layer<false, true >(128, sh_W1, OFF_SH1, hs, hs, ws, ws_s, mg, t, r0, c4);
        glu_layer<false, true >(128, sw,             OFF_STEP + (s * 2) * 256,     hs, hs, ws, ws_s, mg, t, r0, c4);
        glu_layer<false, true >(128, sw + 128 * 256, OFF_STEP + (s * 2 + 1) * 256, hs, hs, ws, ws_s, mg, t, r0, c4);

        // ---- decision_sum += relu(d) (d = hs cols 0..63; same phys layout) ----
#pragma unroll
        for (int i = 0; i < 16; i++) {
            int idx = t + i * 256;      // 4096 elems
            float v = hs[idx];
            ds[idx] += v > 0.f ? v : 0.f;
        }
        __syncthreads();
    }

    // ---- final: out = decision_sum @ out_W + out_b ----
    if (t < 64) {
        float sacc = 0.f;
#pragma unroll
        for (int j = 0; j < 64; j++)
            sacc = fmaf(ds[SWZ(j, t)], out_W[j], sacc);
        out[rowb + t] = sacc + out_b[0];
    }
}

#define SMEM_FLOATS (320*64 + 128*64 + 12288 + 80*64 + 64*80 + 64*64)
#define SMEM_BYTES  (SMEM_FLOATS * 4)

extern "C" void kernel_launch(void* const* d_in, const int* in_sizes, int n_in,
                              void* d_out, int out_size)
{
    const float* x_num   = (const float*)d_in[0];
    const int*   x_cat   = (const int*)  d_in[1];
    const float* emb_W   = (const float*)d_in[2];
    const float* in_bn   = (const float*)d_in[3];
    const float* sh_W0   = (const float*)d_in[4];
    const float* sh_b0   = (const float*)d_in[5];
    const float* sh_bn0  = (const float*)d_in[6];
    const float* sh_W1   = (const float*)d_in[7];
    const float* sh_b1   = (const float*)d_in[8];
    const float* sh_bn1  = (const float*)d_in[9];
    const float* init_W  = (const float*)d_in[10];
    const float* init_b  = (const float*)d_in[11];
    const float* init_bn = (const float*)d_in[12];
    const float* step_W  = (const float*)d_in[13];
    const float* step_b  = (const float*)d_in[14];
    const float* step_bn = (const float*)d_in[15];
    const float* att_W   = (const float*)d_in[16];
    const float* att_b   = (const float*)d_in[17];
    const float* att_bn  = (const float*)d_in[18];
    const float* out_W   = (const float*)d_in[19];
    const float* out_b   = (const float*)d_in[20];
    float* out = (float*)d_out;

    cudaFuncSetAttribute(tabnet_kernel,
                         cudaFuncAttributeMaxDynamicSharedMemorySize, SMEM_BYTES);

    prep_kernel<<<(AC_TOTAL + 255) / 256, 256>>>(
        in_bn, sh_b0, sh_bn0, sh_b1, sh_bn1,
        init_b, init_bn, step_b, step_bn, att_b, att_bn);

    tabnet_kernel<<<BATCH / TM, NTH, SMEM_BYTES>>>(
        x_num, x_cat, emb_W, sh_W0, sh_W1, init_W, step_W,
        att_W, out_W, out_b, out);
}